// round 8
// baseline (speedup 1.0000x reference)
#include <cuda_runtime.h>
#include <cuda_bf16.h>
#include <mma.h>
#include <cstdint>

using namespace nvcuda;

#define T_ROWS    8192
#define K_DIM     4096
#define N_NODES   63
#define DEPTH_    6
#define N_LEAVES  64
#define NB_CLS    10

#define MT        64                   // rows per CTA
#define KC        64                   // k elems per chunk (fp32: 256B/row)
#define NCHUNK    (K_DIM / KC)         // 64
#define NSTAGE    4                    // ring depth
#define LDF       72                   // smem leading dim in fp32 elems
#define ROW_B     (LDF * 4)            // 288 B
#define NT        256                  // 4 consumer + 4 producer warps
#define NBLOCKS   (T_ROWS / MT)        // 128

#define XTILE_B   (MT * ROW_B)         // 18432 B
#define STAGE_B   (2 * XTILE_B)        // X + W = 36864 B
#define DYN_B     (NSTAGE * STAGE_B)   // 147456 B

__device__ float g_partial[NBLOCKS];
__device__ int   g_ticket;

static __device__ __forceinline__ uint32_t smem_u32(const void* p) {
    uint32_t a;
    asm("{ .reg .u64 t; cvta.to.shared.u64 t, %1; cvt.u32.u64 %0, t; }" : "=r"(a) : "l"(p));
    return a;
}
static __device__ __forceinline__ void mbar_init(uint32_t a, uint32_t cnt) {
    asm volatile("mbarrier.init.shared.b64 [%0], %1;" :: "r"(a), "r"(cnt) : "memory");
}
static __device__ __forceinline__ void mbar_arrive(uint32_t a) {
    asm volatile("mbarrier.arrive.shared.b64 _, [%0];" :: "r"(a) : "memory");
}
static __device__ __forceinline__ void wait_parity(uint32_t mbar, uint32_t phase) {
    uint32_t done;
    asm volatile(
        "{\n\t.reg .pred p;\n\t"
        "mbarrier.try_wait.parity.acquire.cta.shared::cta.b64 p, [%1], %2;\n\t"
        "selp.b32 %0, 1, 0, p;\n\t}"
        : "=r"(done) : "r"(mbar), "r"(phase) : "memory");
    if (!done) {
        asm volatile(
            "{\n\t.reg .pred P1;\n\t"
            "W0_%=:\n\t"
            "mbarrier.try_wait.parity.acquire.cta.shared::cta.b64 P1, [%0], %1, 0x989680;\n\t"
            "@P1 bra.uni W1_%=;\n\t"
            "bra.uni W0_%=;\n\t"
            "W1_%=:\n\t}"
            :: "r"(mbar), "r"(phase) : "memory");
    }
}
static __device__ __forceinline__ void cp16(uint32_t dst, const float* src) {
    asm volatile("cp.async.cg.shared.global [%0], [%1], 16;"
                 :: "r"(dst), "l"(src) : "memory");
}

__global__ void __launch_bounds__(NT, 1) sdt_main(
    const float* __restrict__ X, const float* __restrict__ W,
    const float* __restrict__ bias, const float* __restrict__ beta,
    const float* __restrict__ leaf_dist, const float* __restrict__ cls_r,
    float* __restrict__ out)
{
    extern __shared__ __align__(128) unsigned char dynsm[];
    __shared__ __align__(8) unsigned long long full_mb[NSTAGE], empty_mb[NSTAGE];
    __shared__ float leaf_r[N_LEAVES];
    __shared__ float bias_s[N_NODES], beta_s[N_NODES];
    __shared__ float red_s[NT / 32];
    __shared__ int   is_last_s;

    const int tid  = threadIdx.x;
    const int wid  = tid >> 5;
    const int lane = tid & 31;
    const uint32_t dbase = smem_u32(dynsm);
    const long mrow0 = (long)blockIdx.x * MT;

    if (tid < NSTAGE) {
        mbar_init(smem_u32(&full_mb[tid]),  4);   // 4 producer warps
        mbar_init(smem_u32(&empty_mb[tid]), 4);   // 4 consumer warps
    }
    // zero the W pad row (row 63) in every stage — cp.async never writes it
    for (int z = tid; z < NSTAGE * LDF; z += NT) {
        int s = z / LDF, c = z % LDF;
        *reinterpret_cast<float*>(dynsm + s * STAGE_B + XTILE_B + 63 * ROW_B + c * 4) = 0.f;
    }
    if (tid < N_NODES) { bias_s[tid] = bias[tid]; beta_s[tid] = beta[tid]; }
    if (tid < N_LEAVES) {
        const float* ldp = leaf_dist + tid * NB_CLS;
        float mx = ldp[0];
        #pragma unroll
        for (int c = 1; c < NB_CLS; c++) mx = fmaxf(mx, ldp[c]);
        float se = 0.f, sr = 0.f;
        #pragma unroll
        for (int c = 0; c < NB_CLS; c++) {
            float e = __expf(ldp[c] - mx);
            se += e; sr += e * cls_r[c];
        }
        leaf_r[tid] = sr / se;
    }
    __syncthreads();

    wmma::fragment<wmma::accumulator, 16, 16, 8, float> acc[2][2];

    if (wid >= 4) {
        // ===== PRODUCER (warps 4-7): register-free cp.async into 4-stage ring =====
        const int pt = tid - 128;                 // 0..127
        const float* Xg = X + mrow0 * K_DIM;

        for (int i = 0; i < NCHUNK; i++) {
            const int s = i & (NSTAGE - 1);
            if (i >= NSTAGE) wait_parity(smem_u32(&empty_mb[s]), ((i >> 2) - 1) & 1);
            const uint32_t xs = dbase + s * STAGE_B;
            const float* xsrc = Xg + i * KC;
            const float* wsrc = W + i * KC;
            #pragma unroll
            for (int j = 0; j < 8; j++) {          // X: 64 rows x 16 x 16B
                int c = pt + 128 * j;
                int row = c >> 4, col = c & 15;
                cp16(xs + row * ROW_B + col * 16, xsrc + (long)row * K_DIM + col * 4);
            }
            #pragma unroll
            for (int j = 0; j < 8; j++) {          // W: 63 valid rows
                int c = pt + 128 * j;
                int row = c >> 4, col = c & 15;
                if (row < N_NODES)
                    cp16(xs + XTILE_B + row * ROW_B + col * 16, wsrc + (long)row * K_DIM + col * 4);
            }
            asm volatile("cp.async.commit_group;" ::: "memory");
            if (i >= 2) {                          // keep 2 chunk-groups in flight
                asm volatile("cp.async.wait_group 2;" ::: "memory");
                __syncwarp();
                if (lane == 0) mbar_arrive(smem_u32(&full_mb[(i - 2) & (NSTAGE - 1)]));
            }
        }
        asm volatile("cp.async.wait_group 0;" ::: "memory");
        __syncwarp();
        if (lane == 0) {
            mbar_arrive(smem_u32(&full_mb[(NCHUNK - 2) & (NSTAGE - 1)]));
            mbar_arrive(smem_u32(&full_mb[(NCHUNK - 1) & (NSTAGE - 1)]));
        }
    } else {
        // ===== CONSUMER (warps 0-3): TF32 MMA, 32x32 tile per warp =====
        const int mb = (wid & 1) * 32;
        const int nb = (wid >> 1) * 32;
        #pragma unroll
        for (int a = 0; a < 2; a++)
            #pragma unroll
            for (int b = 0; b < 2; b++)
                wmma::fill_fragment(acc[a][b], 0.f);

        for (int i = 0; i < NCHUNK; i++) {
            const int s = i & (NSTAGE - 1);
            wait_parity(smem_u32(&full_mb[s]), (i >> 2) & 1);
            const float* Xs = reinterpret_cast<const float*>(dynsm + s * STAGE_B);
            const float* Ws = reinterpret_cast<const float*>(dynsm + s * STAGE_B + XTILE_B);
            #pragma unroll
            for (int ks = 0; ks < KC / 8; ks++) {
                wmma::fragment<wmma::matrix_a, 16, 16, 8, wmma::precision::tf32, wmma::row_major> fa0, fa1;
                wmma::fragment<wmma::matrix_b, 16, 16, 8, wmma::precision::tf32, wmma::col_major> fb0, fb1;
                wmma::load_matrix_sync(fa0, Xs + (mb)      * LDF + ks * 8, LDF);
                wmma::load_matrix_sync(fa1, Xs + (mb + 16) * LDF + ks * 8, LDF);
                wmma::load_matrix_sync(fb0, Ws + (nb)      * LDF + ks * 8, LDF);
                wmma::load_matrix_sync(fb1, Ws + (nb + 16) * LDF + ks * 8, LDF);
                wmma::mma_sync(acc[0][0], fa0, fb0, acc[0][0]);
                wmma::mma_sync(acc[0][1], fa0, fb1, acc[0][1]);
                wmma::mma_sync(acc[1][0], fa1, fb0, acc[1][0]);
                wmma::mma_sync(acc[1][1], fa1, fb1, acc[1][1]);
            }
            __syncwarp();
            if (lane == 0) mbar_arrive(smem_u32(&empty_mb[s]));
        }
    }

    // ---- epilogue: dump accumulators into stage 0 (ring fully drained) ----
    __syncthreads();
    float* accS = reinterpret_cast<float*>(dynsm);
    if (wid < 4) {
        const int mb = (wid & 1) * 32;
        const int nb = (wid >> 1) * 32;
        #pragma unroll
        for (int a = 0; a < 2; a++)
            #pragma unroll
            for (int b = 0; b < 2; b++)
                wmma::store_matrix_sync(accS + (mb + 16 * a) * LDF + nb + 16 * b,
                                        acc[a][b], LDF, wmma::mem_row_major);
    }
    __syncthreads();

    float rowval = 0.f;
    if (tid < MT) {
        float v[N_LEAVES];
        #pragma unroll
        for (int j = 0; j < N_LEAVES; j++) v[j] = leaf_r[j];
        #pragma unroll
        for (int lvl = DEPTH_ - 1; lvl >= 0; lvl--) {
            int base = (1 << lvl) - 1;
            #pragma unroll
            for (int i = 0; i < (1 << lvl); i++) {
                int n = base + i;
                float z = accS[tid * LDF + n];
                float a = beta_s[n] * (z + bias_s[n]);
                float p = 1.f / (1.f + __expf(-a));
                v[i] = p * v[2 * i] + (1.f - p) * v[2 * i + 1];
            }
        }
        rowval = v[0];
    }

    #pragma unroll
    for (int o = 16; o > 0; o >>= 1) rowval += __shfl_down_sync(0xffffffffu, rowval, o);
    if (lane == 0) red_s[wid] = rowval;
    __syncthreads();
    if (tid == 0) {
        float s = 0.f;
        #pragma unroll
        for (int i = 0; i < NT / 32; i++) s += red_s[i];
        g_partial[blockIdx.x] = s;
        __threadfence();
        int t = atomicAdd(&g_ticket, 1);
        is_last_s = (t == NBLOCKS - 1) ? 1 : 0;
    }
    __syncthreads();

    if (is_last_s && wid == 0) {
        __threadfence();
        float v = g_partial[lane] + g_partial[lane + 32] +
                  g_partial[lane + 64] + g_partial[lane + 96];
        #pragma unroll
        for (int o = 16; o > 0; o >>= 1) v += __shfl_down_sync(0xffffffffu, v, o);
        if (lane == 0) { out[0] = v; g_ticket = 0; }
    }
}

extern "C" void kernel_launch(void* const* d_in, const int* in_sizes, int n_in,
                              void* d_out, int out_size) {
    const float* X         = (const float*)d_in[0];
    const float* W         = (const float*)d_in[1];
    const float* b         = (const float*)d_in[2];
    const float* beta      = (const float*)d_in[3];
    const float* leaf_dist = (const float*)d_in[4];
    const float* cls_r     = (const float*)d_in[5];

    cudaFuncSetAttribute(sdt_main, cudaFuncAttributeMaxDynamicSharedMemorySize, DYN_B);
    sdt_main<<<NBLOCKS, NT, DYN_B>>>(X, W, b, beta, leaf_dist, cls_r, (float*)d_out);
}

// round 9
// speedup vs baseline: 1.8556x; 1.8556x over previous
#include <cuda_runtime.h>
#include <cuda_bf16.h>
#include <mma.h>
#include <cstdint>

using namespace nvcuda;

#define T_ROWS    8192
#define K_DIM     4096
#define N_NODES   63
#define DEPTH_    6
#define N_LEAVES  64
#define NB_CLS    10

#define MT        128                  // rows per CTA
#define KC        64                   // k elems per chunk
#define KSPLIT    2
#define KSLICE    (K_DIM / KSPLIT)     // 2048
#define NCHUNK    (KSLICE / KC)        // 32
#define NSTAGE    4
#define NT        384                  // 4 consumer + 8 producer warps
#define NRB       (T_ROWS / MT)        // 64 row-blocks
#define NBLOCKS   (NRB * KSPLIT)       // 128 CTAs

#define LDH       72                   // bf16 leading dim -> 144 B rows
#define XTILE_B   (MT * LDH * 2)       // 18432 B
#define WTILE_B   (64 * LDH * 2)       // 9216 B
#define STAGE_B   (XTILE_B + WTILE_B)  // 27648 B
#define DYN_B     (NSTAGE * STAGE_B)   // 110592 B
#define LDF       72                   // fp32 acc leading dim

__device__ float g_z[KSPLIT * NRB * MT * 64];   // 4 MB split-K partials
__device__ int   g_rb_ticket[NRB];
__device__ float g_partial[NRB];
__device__ int   g_ticket;

static __device__ __forceinline__ uint32_t smem_u32(const void* p) {
    uint32_t a;
    asm("{ .reg .u64 t; cvta.to.shared.u64 t, %1; cvt.u32.u64 %0, t; }" : "=r"(a) : "l"(p));
    return a;
}
static __device__ __forceinline__ void mbar_init(uint32_t a, uint32_t cnt) {
    asm volatile("mbarrier.init.shared.b64 [%0], %1;" :: "r"(a), "r"(cnt) : "memory");
}
static __device__ __forceinline__ void mbar_arrive(uint32_t a) {
    asm volatile("mbarrier.arrive.shared.b64 _, [%0];" :: "r"(a) : "memory");
}
static __device__ __forceinline__ void wait_parity(uint32_t mbar, uint32_t phase) {
    uint32_t done;
    asm volatile(
        "{\n\t.reg .pred p;\n\t"
        "mbarrier.try_wait.parity.acquire.cta.shared::cta.b64 p, [%1], %2;\n\t"
        "selp.b32 %0, 1, 0, p;\n\t}"
        : "=r"(done) : "r"(mbar), "r"(phase) : "memory");
    if (!done) {
        asm volatile(
            "{\n\t.reg .pred P1;\n\t"
            "W0_%=:\n\t"
            "mbarrier.try_wait.parity.acquire.cta.shared::cta.b64 P1, [%0], %1, 0x989680;\n\t"
            "@P1 bra.uni W1_%=;\n\t"
            "bra.uni W0_%=;\n\t"
            "W1_%=:\n\t}"
            :: "r"(mbar), "r"(phase) : "memory");
    }
}
static __device__ __forceinline__ void sts128(uint32_t a, uint4 v) {
    asm volatile("st.shared.v4.b32 [%0], {%1,%2,%3,%4};"
                 :: "r"(a), "r"(v.x), "r"(v.y), "r"(v.z), "r"(v.w) : "memory");
}
static __device__ __forceinline__ uint4 pack8(float4 a, float4 b) {
    uint4 u; __nv_bfloat162 h;
    h = __floats2bfloat162_rn(a.x, a.y); u.x = *reinterpret_cast<uint32_t*>(&h);
    h = __floats2bfloat162_rn(a.z, a.w); u.y = *reinterpret_cast<uint32_t*>(&h);
    h = __floats2bfloat162_rn(b.x, b.y); u.z = *reinterpret_cast<uint32_t*>(&h);
    h = __floats2bfloat162_rn(b.z, b.w); u.w = *reinterpret_cast<uint32_t*>(&h);
    return u;
}

__global__ void __launch_bounds__(NT, 1) sdt_main(
    const float* __restrict__ X, const float* __restrict__ W,
    const float* __restrict__ bias, const float* __restrict__ beta,
    const float* __restrict__ leaf_dist, const float* __restrict__ cls_r,
    float* __restrict__ out)
{
    extern __shared__ __align__(128) unsigned char dynsm[];
    __shared__ __align__(8) unsigned long long full_mb[NSTAGE], empty_mb[NSTAGE];
    __shared__ float leaf_r[N_LEAVES];
    __shared__ float bias_s[N_NODES], beta_s[N_NODES];
    __shared__ float red_s[NT / 32];
    __shared__ int   flag_s;        // 1 if this CTA runs the rowblock epilogue
    __shared__ int   last_s;        // 1 if this CTA runs the final sum

    const int tid  = threadIdx.x;
    const int wid  = tid >> 5;
    const int lane = tid & 31;
    const int rb   = blockIdx.x >> 1;      // row-block
    const int ks   = blockIdx.x & 1;       // k-split
    const long mrow0 = (long)rb * MT;
    const long koff  = (long)ks * KSLICE;
    const uint32_t dbase = smem_u32(dynsm);

    if (tid < NSTAGE) {
        mbar_init(smem_u32(&full_mb[tid]),  8);   // 8 producer warps arrive
        mbar_init(smem_u32(&empty_mb[tid]), 4);   // 4 consumer warps arrive
    }
    if (tid < N_NODES) { bias_s[tid] = bias[tid]; beta_s[tid] = beta[tid]; }
    if (tid < N_LEAVES) {
        const float* ldp = leaf_dist + tid * NB_CLS;
        float mx = ldp[0];
        #pragma unroll
        for (int c = 1; c < NB_CLS; c++) mx = fmaxf(mx, ldp[c]);
        float se = 0.f, sr = 0.f;
        #pragma unroll
        for (int c = 0; c < NB_CLS; c++) {
            float e = __expf(ldp[c] - mx);
            se += e; sr += e * cls_r[c];
        }
        leaf_r[tid] = sr / se;
    }
    __syncthreads();

    wmma::fragment<wmma::accumulator, 16, 16, 16, float> acc[2][4];

    if (wid >= 4) {
        // ===== PRODUCERS (warps 4-11, 256 threads) =====
        // X chunk: 128 rows x 8 x16B-bf16 = 1024 chunks -> 4/thread (2 LDG.128 each)
        // W chunk: 64 rows  x 8           = 512  chunks -> 2/thread
        const int pt = tid - 128;            // 0..255
        const float* Xb = X + mrow0 * K_DIM + koff;
        const float* Wb = W + koff;

        float4 xa[8], wa[4];
        auto ldchunk = [&](int i) {
            #pragma unroll
            for (int j = 0; j < 4; j++) {
                int c = pt + 256 * j;
                int row = c >> 3, c8 = c & 7;
                const float4* p = reinterpret_cast<const float4*>(
                    Xb + (long)row * K_DIM + i * KC + c8 * 8);
                xa[2 * j] = p[0]; xa[2 * j + 1] = p[1];
            }
            #pragma unroll
            for (int j = 0; j < 2; j++) {
                int c = pt + 256 * j;
                int row = c >> 3, c8 = c & 7;
                if (row < N_NODES) {
                    const float4* p = reinterpret_cast<const float4*>(
                        Wb + (long)row * K_DIM + i * KC + c8 * 8);
                    wa[2 * j] = p[0]; wa[2 * j + 1] = p[1];
                } else {
                    wa[2 * j] = make_float4(0.f, 0.f, 0.f, 0.f);
                    wa[2 * j + 1] = wa[2 * j];
                }
            }
        };
        auto stchunk = [&](int s) {
            uint32_t base = dbase + s * STAGE_B;
            #pragma unroll
            for (int j = 0; j < 4; j++) {
                int c = pt + 256 * j;
                int row = c >> 3, c8 = c & 7;
                sts128(base + row * (LDH * 2) + c8 * 16, pack8(xa[2 * j], xa[2 * j + 1]));
            }
            #pragma unroll
            for (int j = 0; j < 2; j++) {
                int c = pt + 256 * j;
                int row = c >> 3, c8 = c & 7;
                sts128(base + XTILE_B + row * (LDH * 2) + c8 * 16, pack8(wa[2 * j], wa[2 * j + 1]));
            }
        };

        ldchunk(0);
        for (int i = 0; i < NCHUNK; i++) {
            const int s = i & (NSTAGE - 1);
            if (i >= NSTAGE) wait_parity(smem_u32(&empty_mb[s]), ((i >> 2) - 1) & 1);
            stchunk(s);
            __syncwarp();
            if (lane == 0) mbar_arrive(smem_u32(&full_mb[s]));
            if (i + 1 < NCHUNK) ldchunk(i + 1);   // overlap next chunk's DRAM latency
        }
    } else {
        // ===== CONSUMERS (warps 0-3): each owns 32 rows x 64 cols =====
        const int mb = wid * 32;
        #pragma unroll
        for (int a = 0; a < 2; a++)
            #pragma unroll
            for (int b = 0; b < 4; b++)
                wmma::fill_fragment(acc[a][b], 0.f);

        for (int i = 0; i < NCHUNK; i++) {
            const int s = i & (NSTAGE - 1);
            wait_parity(smem_u32(&full_mb[s]), (i >> 2) & 1);
            const __nv_bfloat16* Xs = reinterpret_cast<const __nv_bfloat16*>(dynsm + s * STAGE_B);
            const __nv_bfloat16* Ws = reinterpret_cast<const __nv_bfloat16*>(dynsm + s * STAGE_B + XTILE_B);
            #pragma unroll
            for (int kk = 0; kk < KC / 16; kk++) {
                wmma::fragment<wmma::matrix_a, 16, 16, 16, __nv_bfloat16, wmma::row_major> fa0, fa1;
                wmma::load_matrix_sync(fa0, Xs + (mb)      * LDH + kk * 16, LDH);
                wmma::load_matrix_sync(fa1, Xs + (mb + 16) * LDH + kk * 16, LDH);
                #pragma unroll
                for (int b = 0; b < 4; b++) {
                    wmma::fragment<wmma::matrix_b, 16, 16, 16, __nv_bfloat16, wmma::col_major> fb;
                    wmma::load_matrix_sync(fb, Ws + (b * 16) * LDH + kk * 16, LDH);
                    wmma::mma_sync(acc[0][b], fa0, fb, acc[0][b]);
                    wmma::mma_sync(acc[1][b], fa1, fb, acc[1][b]);
                }
            }
            __syncwarp();
            if (lane == 0) mbar_arrive(smem_u32(&empty_mb[s]));
        }
    }

    // ===== dump accumulators (ring fully drained) =====
    __syncthreads();
    float* accS = reinterpret_cast<float*>(dynsm);   // 128 x LDF fp32 = 36 KB
    if (wid < 4) {
        const int mb = wid * 32;
        #pragma unroll
        for (int a = 0; a < 2; a++)
            #pragma unroll
            for (int b = 0; b < 4; b++)
                wmma::store_matrix_sync(accS + (mb + 16 * a) * LDF + 16 * b,
                                        acc[a][b], LDF, wmma::mem_row_major);
    }
    __syncthreads();

    // write partial Z to scratch (coalesced)
    float* zdst = g_z + ((long)ks * NRB + rb) * (MT * 64);
    for (int idx = tid; idx < MT * 64; idx += NT) {
        int row = idx >> 6, col = idx & 63;
        zdst[idx] = accS[row * LDF + col];
    }
    __threadfence();
    if (tid == 0) {
        int t = atomicAdd(&g_rb_ticket[rb], 1);
        flag_s = (t == 1) ? 1 : 0;
        if (t == 1) g_rb_ticket[rb] = 0;          // reset for next replay
    }
    __syncthreads();

    if (flag_s) {
        // second-arriving CTA: combine split-K partials, run tree epilogue
        __threadfence();
        const float* zoth = g_z + ((long)(ks ^ 1) * NRB + rb) * (MT * 64);
        float rowval = 0.f;
        if (tid < MT) {
            float v[N_LEAVES];
            #pragma unroll
            for (int j = 0; j < N_LEAVES; j++) v[j] = leaf_r[j];
            #pragma unroll
            for (int lvl = DEPTH_ - 1; lvl >= 0; lvl--) {
                int base = (1 << lvl) - 1;
                #pragma unroll
                for (int i = 0; i < (1 << lvl); i++) {
                    int n = base + i;
                    float z = accS[tid * LDF + n] + zoth[tid * 64 + n];
                    float a = beta_s[n] * (z + bias_s[n]);
                    float p = 1.f / (1.f + __expf(-a));
                    v[i] = p * v[2 * i] + (1.f - p) * v[2 * i + 1];
                }
            }
            rowval = v[0];
        }
        #pragma unroll
        for (int o = 16; o > 0; o >>= 1) rowval += __shfl_down_sync(0xffffffffu, rowval, o);
        if (lane == 0) red_s[wid] = rowval;
        __syncthreads();
        if (tid == 0) {
            float s = 0.f;
            #pragma unroll
            for (int i = 0; i < 4; i++) s += red_s[i];   // only warps 0-3 carry rows
            g_partial[rb] = s;
            __threadfence();
            int t = atomicAdd(&g_ticket, 1);
            last_s = (t == NRB - 1) ? 1 : 0;
            if (t == NRB - 1) g_ticket = 0;              // reset for next replay
        }
        __syncthreads();

        if (last_s && wid == 0) {
            __threadfence();
            float v = g_partial[lane] + g_partial[lane + 32];
            #pragma unroll
            for (int o = 16; o > 0; o >>= 1) v += __shfl_down_sync(0xffffffffu, v, o);
            if (lane == 0) out[0] = v;
        }
    }
}

extern "C" void kernel_launch(void* const* d_in, const int* in_sizes, int n_in,
                              void* d_out, int out_size) {
    const float* X         = (const float*)d_in[0];
    const float* W         = (const float*)d_in[1];
    const float* b         = (const float*)d_in[2];
    const float* beta      = (const float*)d_in[3];
    const float* leaf_dist = (const float*)d_in[4];
    const float* cls_r     = (const float*)d_in[5];

    cudaFuncSetAttribute(sdt_main, cudaFuncAttributeMaxDynamicSharedMemorySize, DYN_B);
    sdt_main<<<NBLOCKS, NT, DYN_B>>>(X, W, b, beta, leaf_dist, cls_r, (float*)d_out);
}

// round 10
// speedup vs baseline: 1.8818x; 1.0142x over previous
#include <cuda_runtime.h>
#include <cuda_bf16.h>
#include <mma.h>
#include <cstdint>

using namespace nvcuda;

#define T_ROWS    8192
#define K_DIM     4096
#define N_NODES   63
#define DEPTH_    6
#define N_LEAVES  64
#define NB_CLS    10

#define MT        128                  // rows per CTA
#define KC        64                   // k elems per chunk
#define KSPLIT    2
#define KSLICE    (K_DIM / KSPLIT)     // 2048
#define NCHUNK    (KSLICE / KC)        // 32
#define NSTAGE    4
#define NT        512                  // 8 consumer + 8 producer warps
#define NRB       (T_ROWS / MT)        // 64 row-blocks
#define NBLOCKS   (NRB * KSPLIT)       // 128 CTAs

#define LDH       72                   // bf16 leading dim -> 144 B rows
#define XTILE_B   (MT * LDH * 2)       // 18432 B
#define WTILE_B   (64 * LDH * 2)       // 9216 B
#define STAGE_B   (XTILE_B + WTILE_B)  // 27648 B
#define DYN_B     (NSTAGE * STAGE_B)   // 110592 B
#define LDF       72

__device__ float g_z[KSPLIT * NRB * MT * 64];
__device__ int   g_rb_ticket[NRB];
__device__ float g_partial[NRB];
__device__ int   g_ticket;

static __device__ __forceinline__ uint32_t smem_u32(const void* p) {
    uint32_t a;
    asm("{ .reg .u64 t; cvta.to.shared.u64 t, %1; cvt.u32.u64 %0, t; }" : "=r"(a) : "l"(p));
    return a;
}
static __device__ __forceinline__ void mbar_init(uint32_t a, uint32_t cnt) {
    asm volatile("mbarrier.init.shared.b64 [%0], %1;" :: "r"(a), "r"(cnt) : "memory");
}
static __device__ __forceinline__ void mbar_arrive(uint32_t a) {
    asm volatile("mbarrier.arrive.shared.b64 _, [%0];" :: "r"(a) : "memory");
}
static __device__ __forceinline__ void wait_parity(uint32_t mbar, uint32_t phase) {
    uint32_t done;
    asm volatile(
        "{\n\t.reg .pred p;\n\t"
        "mbarrier.try_wait.parity.acquire.cta.shared::cta.b64 p, [%1], %2;\n\t"
        "selp.b32 %0, 1, 0, p;\n\t}"
        : "=r"(done) : "r"(mbar), "r"(phase) : "memory");
    if (!done) {
        asm volatile(
            "{\n\t.reg .pred P1;\n\t"
            "W0_%=:\n\t"
            "mbarrier.try_wait.parity.acquire.cta.shared::cta.b64 P1, [%0], %1, 0x989680;\n\t"
            "@P1 bra.uni W1_%=;\n\t"
            "bra.uni W0_%=;\n\t"
            "W1_%=:\n\t}"
            :: "r"(mbar), "r"(phase) : "memory");
    }
}
static __device__ __forceinline__ void sts128(uint32_t a, uint4 v) {
    asm volatile("st.shared.v4.b32 [%0], {%1,%2,%3,%4};"
                 :: "r"(a), "r"(v.x), "r"(v.y), "r"(v.z), "r"(v.w) : "memory");
}
static __device__ __forceinline__ uint4 pack8(float4 a, float4 b) {
    uint4 u; __nv_bfloat162 h;
    h = __floats2bfloat162_rn(a.x, a.y); u.x = *reinterpret_cast<uint32_t*>(&h);
    h = __floats2bfloat162_rn(a.z, a.w); u.y = *reinterpret_cast<uint32_t*>(&h);
    h = __floats2bfloat162_rn(b.x, b.y); u.z = *reinterpret_cast<uint32_t*>(&h);
    h = __floats2bfloat162_rn(b.z, b.w); u.w = *reinterpret_cast<uint32_t*>(&h);
    return u;
}

// producer staging: X 4 slots (8 float4), W 2 slots (4 float4) per thread
#define LDCHUNK(xa, wa, i) do {                                               \
    _Pragma("unroll")                                                         \
    for (int j = 0; j < 4; j++) {                                             \
        int c = pt + 256 * j;                                                 \
        int row = c >> 3, c8 = c & 7;                                         \
        const float4* p = reinterpret_cast<const float4*>(                    \
            Xb + (long)row * K_DIM + (i) * KC + c8 * 8);                      \
        xa[2 * j] = p[0]; xa[2 * j + 1] = p[1];                               \
    }                                                                         \
    _Pragma("unroll")                                                         \
    for (int j = 0; j < 2; j++) {                                             \
        int c = pt + 256 * j;                                                 \
        int row = c >> 3, c8 = c & 7;                                         \
        if (row < N_NODES) {                                                  \
            const float4* p = reinterpret_cast<const float4*>(                \
                Wb + (long)row * K_DIM + (i) * KC + c8 * 8);                  \
            wa[2 * j] = p[0]; wa[2 * j + 1] = p[1];                           \
        } else {                                                              \
            wa[2 * j] = make_float4(0.f, 0.f, 0.f, 0.f);                      \
            wa[2 * j + 1] = wa[2 * j];                                        \
        }                                                                     \
    }                                                                         \
} while (0)

#define STCHUNK(xa, wa, s) do {                                               \
    uint32_t base = dbase + (s) * STAGE_B;                                    \
    _Pragma("unroll")                                                         \
    for (int j = 0; j < 4; j++) {                                             \
        int c = pt + 256 * j;                                                 \
        int row = c >> 3, c8 = c & 7;                                         \
        sts128(base + row * (LDH * 2) + c8 * 16, pack8(xa[2 * j], xa[2 * j + 1])); \
    }                                                                         \
    _Pragma("unroll")                                                         \
    for (int j = 0; j < 2; j++) {                                             \
        int c = pt + 256 * j;                                                 \
        int row = c >> 3, c8 = c & 7;                                         \
        sts128(base + XTILE_B + row * (LDH * 2) + c8 * 16,                    \
               pack8(wa[2 * j], wa[2 * j + 1]));                              \
    }                                                                         \
} while (0)

__global__ void __launch_bounds__(NT, 1) sdt_main(
    const float* __restrict__ X, const float* __restrict__ W,
    const float* __restrict__ bias, const float* __restrict__ beta,
    const float* __restrict__ leaf_dist, const float* __restrict__ cls_r,
    float* __restrict__ out)
{
    extern __shared__ __align__(128) unsigned char dynsm[];
    __shared__ __align__(8) unsigned long long full_mb[NSTAGE], empty_mb[NSTAGE];
    __shared__ float leaf_r[N_LEAVES];
    __shared__ float bias_s[N_NODES], beta_s[N_NODES];
    __shared__ float red_s[NT / 32];
    __shared__ int   flag_s, last_s;

    const int tid  = threadIdx.x;
    const int wid  = tid >> 5;
    const int lane = tid & 31;
    const int rb   = blockIdx.x >> 1;
    const int ks   = blockIdx.x & 1;
    const long mrow0 = (long)rb * MT;
    const long koff  = (long)ks * KSLICE;
    const uint32_t dbase = smem_u32(dynsm);

    if (tid < NSTAGE) {
        mbar_init(smem_u32(&full_mb[tid]),  8);   // 8 producer warps
        mbar_init(smem_u32(&empty_mb[tid]), 8);   // 8 consumer warps
    }
    if (tid < N_NODES) { bias_s[tid] = bias[tid]; beta_s[tid] = beta[tid]; }
    if (tid < N_LEAVES) {
        const float* ldp = leaf_dist + tid * NB_CLS;
        float mx = ldp[0];
        #pragma unroll
        for (int c = 1; c < NB_CLS; c++) mx = fmaxf(mx, ldp[c]);
        float se = 0.f, sr = 0.f;
        #pragma unroll
        for (int c = 0; c < NB_CLS; c++) {
            float e = __expf(ldp[c] - mx);
            se += e; sr += e * cls_r[c];
        }
        leaf_r[tid] = sr / se;
    }
    __syncthreads();

    wmma::fragment<wmma::accumulator, 16, 16, 16, float> acc[2][2];

    if (wid >= 8) {
        // ===== PRODUCERS (warps 8-15, 256 threads), prefetch distance 2 =====
        const int pt = tid - 256;
        const float* Xb = X + mrow0 * K_DIM + koff;
        const float* Wb = W + koff;

        float4 xaA[8], waA[4], xaB[8], waB[4];
        LDCHUNK(xaA, waA, 0);
        LDCHUNK(xaB, waB, 1);
        for (int i = 0; i < NCHUNK; i += 2) {
            // chunk i (buffer A)
            {
                const int s = i & (NSTAGE - 1);
                if (i >= NSTAGE) wait_parity(smem_u32(&empty_mb[s]), ((i >> 2) - 1) & 1);
                STCHUNK(xaA, waA, s);
                __syncwarp();
                if (lane == 0) mbar_arrive(smem_u32(&full_mb[s]));
                if (i + 2 < NCHUNK) LDCHUNK(xaA, waA, i + 2);
            }
            // chunk i+1 (buffer B)
            {
                const int i1 = i + 1;
                const int s = i1 & (NSTAGE - 1);
                if (i1 >= NSTAGE) wait_parity(smem_u32(&empty_mb[s]), ((i1 >> 2) - 1) & 1);
                STCHUNK(xaB, waB, s);
                __syncwarp();
                if (lane == 0) mbar_arrive(smem_u32(&full_mb[s]));
                if (i1 + 2 < NCHUNK) LDCHUNK(xaB, waB, i1 + 2);
            }
        }
    } else {
        // ===== CONSUMERS (warps 0-7): each 32 rows x 32 cols =====
        const int mb = (wid & 3) * 32;
        const int nb = (wid >> 2) * 32;
        #pragma unroll
        for (int a = 0; a < 2; a++)
            #pragma unroll
            for (int b = 0; b < 2; b++)
                wmma::fill_fragment(acc[a][b], 0.f);

        for (int i = 0; i < NCHUNK; i++) {
            const int s = i & (NSTAGE - 1);
            wait_parity(smem_u32(&full_mb[s]), (i >> 2) & 1);
            const __nv_bfloat16* Xs = reinterpret_cast<const __nv_bfloat16*>(dynsm + s * STAGE_B);
            const __nv_bfloat16* Ws = reinterpret_cast<const __nv_bfloat16*>(dynsm + s * STAGE_B + XTILE_B);
            #pragma unroll
            for (int kk = 0; kk < KC / 16; kk++) {
                wmma::fragment<wmma::matrix_a, 16, 16, 16, __nv_bfloat16, wmma::row_major> fa0, fa1;
                wmma::fragment<wmma::matrix_b, 16, 16, 16, __nv_bfloat16, wmma::col_major> fb0, fb1;
                wmma::load_matrix_sync(fa0, Xs + (mb)      * LDH + kk * 16, LDH);
                wmma::load_matrix_sync(fa1, Xs + (mb + 16) * LDH + kk * 16, LDH);
                wmma::load_matrix_sync(fb0, Ws + (nb)      * LDH + kk * 16, LDH);
                wmma::load_matrix_sync(fb1, Ws + (nb + 16) * LDH + kk * 16, LDH);
                wmma::mma_sync(acc[0][0], fa0, fb0, acc[0][0]);
                wmma::mma_sync(acc[0][1], fa0, fb1, acc[0][1]);
                wmma::mma_sync(acc[1][0], fa1, fb0, acc[1][0]);
                wmma::mma_sync(acc[1][1], fa1, fb1, acc[1][1]);
            }
            __syncwarp();
            if (lane == 0) mbar_arrive(smem_u32(&empty_mb[s]));
        }
    }

    // ===== dump accumulators =====
    __syncthreads();
    float* accS = reinterpret_cast<float*>(dynsm);
    if (wid < 8) {
        const int mb = (wid & 3) * 32;
        const int nb = (wid >> 2) * 32;
        #pragma unroll
        for (int a = 0; a < 2; a++)
            #pragma unroll
            for (int b = 0; b < 2; b++)
                wmma::store_matrix_sync(accS + (mb + 16 * a) * LDF + nb + 16 * b,
                                        acc[a][b], LDF, wmma::mem_row_major);
    }
    __syncthreads();

    // write partial Z (coalesced)
    float* zdst = g_z + ((long)ks * NRB + rb) * (MT * 64);
    for (int idx = tid; idx < MT * 64; idx += NT) {
        int row = idx >> 6, col = idx & 63;
        zdst[idx] = accS[row * LDF + col];
    }
    __threadfence();
    if (tid == 0) {
        int t = atomicAdd(&g_rb_ticket[rb], 1);
        flag_s = (t == 1) ? 1 : 0;
        if (t == 1) g_rb_ticket[rb] = 0;
    }
    __syncthreads();

    if (flag_s) {
        __threadfence();
        const float* zoth = g_z + ((long)(ks ^ 1) * NRB + rb) * (MT * 64);
        float rowval = 0.f;
        if (tid < MT) {
            float v[N_LEAVES];
            #pragma unroll
            for (int j = 0; j < N_LEAVES; j++) v[j] = leaf_r[j];
            #pragma unroll
            for (int lvl = DEPTH_ - 1; lvl >= 0; lvl--) {
                int base = (1 << lvl) - 1;
                #pragma unroll
                for (int i = 0; i < (1 << lvl); i++) {
                    int n = base + i;
                    float z = accS[tid * LDF + n] + zoth[tid * 64 + n];
                    float a = beta_s[n] * (z + bias_s[n]);
                    float p = 1.f / (1.f + __expf(-a));
                    v[i] = p * v[2 * i] + (1.f - p) * v[2 * i + 1];
                }
            }
            rowval = v[0];
        }
        #pragma unroll
        for (int o = 16; o > 0; o >>= 1) rowval += __shfl_down_sync(0xffffffffu, rowval, o);
        if (lane == 0) red_s[wid] = rowval;
        __syncthreads();
        if (tid == 0) {
            float s = 0.f;
            #pragma unroll
            for (int i = 0; i < 4; i++) s += red_s[i];   // rows live in warps 0-3
            g_partial[rb] = s;
            __threadfence();
            int t = atomicAdd(&g_ticket, 1);
            last_s = (t == NRB - 1) ? 1 : 0;
            if (t == NRB - 1) g_ticket = 0;
        }
        __syncthreads();

        if (last_s && wid == 0) {
            __threadfence();
            float v = g_partial[lane] + g_partial[lane + 32];
            #pragma unroll
            for (int o = 16; o > 0; o >>= 1) v += __shfl_down_sync(0xffffffffu, v, o);
            if (lane == 0) out[0] = v;
        }
    }
}

extern "C" void kernel_launch(void* const* d_in, const int* in_sizes, int n_in,
                              void* d_out, int out_size) {
    const float* X         = (const float*)d_in[0];
    const float* W         = (const float*)d_in[1];
    const float* b         = (const float*)d_in[2];
    const float* beta      = (const float*)d_in[3];
    const float* leaf_dist = (const float*)d_in[4];
    const float* cls_r     = (const float*)d_in[5];

    cudaFuncSetAttribute(sdt_main, cudaFuncAttributeMaxDynamicSharedMemorySize, DYN_B);
    sdt_main<<<NBLOCKS, NT, DYN_B>>>(X, W, b, beta, leaf_dist, cls_r, (float*)d_out);
}